// round 15
// baseline (speedup 1.0000x reference)
#include <cuda_runtime.h>
#include <cuda_fp16.h>
#include <math.h>
#include <stdint.h>

// Problem shapes (fixed by the dataset)
#define Bv   32
#define Sv   4096
#define BSv  (Bv * Sv)      // 131072 rows
#define Dv   768            // K
#define Hv   1024           // N

#define BMt  128            // CTA M tile
#define BNt  256            // CTA N tile
#define NTt  (Hv / BNt)     // 4 N-tiles
#define NCH  (Dv / 32)      // 24 k-chunks of 32
#define NMT  (BSv / BMt)    // 1024 M tiles

// smem layout (float indices) -- 2-stage pipeline
#define A_BUF_F 4096        // one A stage: 2sp x 8mblk x 2ks x 32slot x 16B
#define B_BUF_F 8192        // one B stage: 32nblk x 2ks x 32slot x 16B (sp0|sp1)
#define OFF_B   8192        // after 2 A stages
#define OFF_SHB 24576       // after 2 B stages
#define OFF_SW2 24832
#define OFF_RED 25088       // 128 x 8 floats
#define SMEM_FLOATS 26112
#define SMEM_BYTES  (SMEM_FLOATS * 4)   // 104448

// ---------------- scratch (static device globals; no allocation) ----------
__device__ float g_scores[BSv];
__device__ float g_part[NTt * BSv];
// W split into 2 fp16 parts, FRAGMENT-MAJOR, splits interleaved per 16B slot:
// [kc 24][nblk 128][ks 2][slot 32][sp0: 4 halfs | sp1: 4 halfs]
__device__ __align__(16) __half g_Wf[24 * 128 * 2 * 32 * 8];
// A (LN-normalized, 2-way fp16 split), FRAGMENT-MAJOR per (mtile, kc):
// [mtile 1024][kc 24][16KB fragment buffer (1024 x uint4)]
__device__ uint4 g_Af[(size_t)NMT * NCH * 1024];   // 402MB
__device__ float g_hbias[Hv];

// ---------------- helpers ---------------------------------------------------
#define MMA_F16(c, a, b)                                                        \
    asm volatile("mma.sync.aligned.m16n8k16.row.col.f32.f16.f16.f32 "          \
                 "{%0,%1,%2,%3}, {%4,%5,%6,%7}, {%8,%9}, {%0,%1,%2,%3};"        \
                 : "+f"((c)[0]), "+f"((c)[1]), "+f"((c)[2]), "+f"((c)[3])       \
                 : "r"((a)[0]), "r"((a)[1]), "r"((a)[2]), "r"((a)[3]),          \
                   "r"((b)[0]), "r"((b)[1]))

__device__ __forceinline__ uint32_t pack_split_lo(float x0, float x1,
                                                  uint32_t &lo2) {
    __half h0 = __float2half_rn(x0), h1 = __float2half_rn(x1);
    __half r0 = __float2half_rn(x0 - __half2float(h0));
    __half r1 = __float2half_rn(x1 - __half2float(h1));
    lo2 = (uint32_t)__half_as_ushort(r0) | ((uint32_t)__half_as_ushort(r1) << 16);
    return (uint32_t)__half_as_ushort(h0) | ((uint32_t)__half_as_ushort(h1) << 16);
}

__device__ __forceinline__ float gelu_exact(float x) {
    return 0.5f * x * (1.0f + erff(x * 0.7071067811865475f));
}
__device__ __forceinline__ float softplusf(float x) {
    return fmaxf(x, 0.0f) + log1pf(expf(-fabsf(x)));
}

// ---------------- prep: fold ln_g into W1, fp16 split, frag-major ---------
__global__ void split_w_frag(const float* __restrict__ w1, const float* __restrict__ lng) {
    int i = blockIdx.x * 256 + threadIdx.x;     // i < Hv*Dv
    int n = i / Dv, k = i % Dv;
    float w = w1[i] * lng[k];
    __half h1 = __float2half_rn(w);
    __half h2 = __float2half_rn(w - __half2float(h1));
    int kc = k >> 5, kl = k & 31, ks = kl >> 4, kk = kl & 15;
    int tig = (kk & 7) >> 1, breg = kk >> 3, lo = kk & 1;
    int nblk = n >> 3, gg = n & 7, slot = tig * 8 + gg;
    size_t base = ((((size_t)kc * 128 + nblk) * 2 + ks) * 32 + slot) * 8
                  + breg * 2 + lo;
    g_Wf[base]     = h1;
    g_Wf[base + 4] = h2;
}

__global__ void prep_hbias(const float* __restrict__ w1, const float* __restrict__ lnb,
                           const float* __restrict__ b1) {
    int h    = blockIdx.x * 8 + (threadIdx.x >> 5);
    int lane = threadIdx.x & 31;
    const float* wr = w1 + (size_t)h * Dv;
    float s = 0.0f;
    for (int d = lane; d < Dv; d += 32) s = fmaf(lnb[d], wr[d], s);
#pragma unroll
    for (int o = 16; o; o >>= 1) s += __shfl_xor_sync(0xffffffffu, s, o);
    if (lane == 0) g_hbias[h] = s + b1[h];
}

// ---------------- fused: LN stats + fp16 split of A, fragment-major -------
// One block per mtile. Pass 1: row stats (DRAM read, 384KB). Pass 2: re-read
// (L2-hot) per kc, split, stage in smem, coalesced write to g_Af.
__global__ void __launch_bounds__(256) ln_split_fused(const float* __restrict__ emb,
                                                      const float* __restrict__ attn) {
    __shared__ float sstat[512];
    __shared__ float sAr[128], tAr[128];
    __shared__ uint32_t sbuf[4096];
    int mtile = blockIdx.x;
    int tid = threadIdx.x;
    int mm = tid & 127, q2 = tid >> 7;
    int mrow = mtile * BMt + mm;
    float at = attn[mrow];

    // pass 1: stats (2 threads per row, each reads 384 floats)
    {
        const float4* ev = (const float4*)(emb + (size_t)mrow * Dv + q2 * 384);
        float s = 0.0f, ss = 0.0f;
#pragma unroll 4
        for (int j = 0; j < 96; j++) {
            float4 v = ev[j];
            float a = v.x * at, b = v.y * at, c = v.z * at, d = v.w * at;
            s += a + b + c + d;
            ss = fmaf(a, a, ss); ss = fmaf(b, b, ss);
            ss = fmaf(c, c, ss); ss = fmaf(d, d, ss);
        }
        sstat[tid] = s;
        sstat[256 + tid] = ss;
    }
    __syncthreads();
    if (tid < 128) {
        float s  = sstat[tid] + sstat[tid + 128];
        float ss = sstat[256 + tid] + sstat[384 + tid];
        float mu  = s * (1.0f / Dv);
        float var = fmaxf(ss * (1.0f / Dv) - mu * mu, 0.0f);
        float rstd = 1.0f / sqrtf(var + 1e-5f);
        sAr[tid] = at * rstd;      // row tid of this mtile (mm==tid here)
        tAr[tid] = mu * rstd;
    }
    __syncthreads();
    float sA = sAr[mm], tA = tAr[mm];
    int gA = mm & 7, hiA = (mm >> 3) & 1, mblkA = mm >> 4;

    // pass 2: per-kc split + fragment staging + coalesced store
#pragma unroll 1
    for (int kc = 0; kc < NCH; kc++) {
        const float4* ea = (const float4*)(emb + (size_t)mrow * Dv + kc * 32 + q2 * 16);
        float4 v0 = ea[0], v1 = ea[1], v2 = ea[2], v3 = ea[3];
        float av[16] = {v0.x, v0.y, v0.z, v0.w, v1.x, v1.y, v1.z, v1.w,
                        v2.x, v2.y, v2.z, v2.w, v3.x, v3.y, v3.z, v3.w};
#pragma unroll
        for (int c8 = 0; c8 < 2; c8++) {
#pragma unroll
            for (int t = 0; t < 4; t++) {
                float x0 = fmaf(av[c8 * 8 + 2 * t], sA, -tA);
                float x1 = fmaf(av[c8 * 8 + 2 * t + 1], sA, -tA);
                uint32_t p2;
                uint32_t p1 = pack_split_lo(x0, x1, p2);
                int s0 = ((mblkA * 2 + q2) * 32 + t * 8 + gA) * 4 + c8 * 2 + hiA;
                sbuf[s0]        = p1;
                sbuf[s0 + 2048] = p2;
            }
        }
        __syncthreads();
        const uint4* sb4 = (const uint4*)sbuf;
        uint4* dst = g_Af + ((size_t)mtile * NCH + kc) * 1024;
#pragma unroll
        for (int i = 0; i < 4; i++) dst[tid + i * 256] = sb4[tid + i * 256];
        __syncthreads();
    }
}

// ---------------- 3xFP16 GEMM + GELU + w2-dot ------------------------------
// CTA 128x256, 512 threads, 16 warps (2x8), warp tile 64x32, mma m16n8k16,
// products A1B1 + A1B2 + A2B1. A-fragment registers REUSED across splits to
// stay under 128 regs (no spills, 4 warps/SMSP). R13's proven 2-stage
// schedule: produce c+1, consume c, wait+sync at loop end.

__global__ void __launch_bounds__(512, 1)
gemm_fp16(const float* __restrict__ w2) {
    extern __shared__ float smf[];
    uint32_t smemA_addr = (uint32_t)__cvta_generic_to_shared(&smf[0]);
    uint32_t smemB_addr = (uint32_t)__cvta_generic_to_shared(&smf[OFF_B]);

    int nt = blockIdx.x, mt = blockIdx.y;
    int n0 = nt * BNt;
    int tid = threadIdx.x;
    int lane = tid & 31, wid = tid >> 5;
    int warp_m = wid >> 3, warp_n = wid & 7;     // 2 x 8
    int g = lane >> 2, tig = lane & 3;
    int pc = tig * 8 + g;                         // fragment slot index

    if (tid < BNt) {
        smf[OFF_SHB + tid] = g_hbias[n0 + tid];
        smf[OFF_SW2 + tid] = w2[n0 + tid];
    }

    const uint4* aBase = g_Af + (size_t)mt * NCH * 1024;

// A: 1024 lines (2/thread). B: 2048 lines (4/thread). One commit group.
#define PRODUCE(KC, BUF)                                                        \
    do {                                                                        \
        const uint4* asrc_ = aBase + (KC) * 1024;                               \
        _Pragma("unroll")                                                       \
        for (int i_ = 0; i_ < 2; i_++) {                                        \
            int L_ = i_ * 512 + tid;                                            \
            uint32_t sa_ = smemA_addr + (uint32_t)((BUF) * 16384 + L_ * 16);    \
            asm volatile("cp.async.cg.shared.global [%0], [%1], 16;"            \
                         :: "r"(sa_), "l"(asrc_ + L_) : "memory");              \
        }                                                                       \
        _Pragma("unroll")                                                       \
        for (int i_ = 0; i_ < 4; i_++) {                                        \
            int L_ = i_ * 512 + tid;                                            \
            int slot_ = L_ & 31, ks_ = (L_ >> 5) & 1, nbl_ = L_ >> 6;           \
            size_t gidx_ = ((((size_t)(KC) * 128 + nt * 32 + nbl_) * 2 + ks_)   \
                            * 32 + slot_) * 8;                                  \
            uint32_t sb_ = smemB_addr + (uint32_t)((BUF) * 32768 + L_ * 16);    \
            asm volatile("cp.async.cg.shared.global [%0], [%1], 16;"            \
                         :: "r"(sb_), "l"(g_Wf + gidx_) : "memory");            \
        }                                                                       \
        asm volatile("cp.async.commit_group;" ::: "memory");                    \
    } while (0)

    float acc[4][4][4];
#pragma unroll
    for (int tm = 0; tm < 4; tm++)
#pragma unroll
        for (int tn = 0; tn < 4; tn++)
#pragma unroll
            for (int e = 0; e < 4; e++) acc[tm][tn][e] = 0.0f;

    PRODUCE(0, 0);
    asm volatile("cp.async.wait_group 0;" ::: "memory");
    __syncthreads();

    int st = 0;
#pragma unroll 1
    for (int c = 0; c < NCH; c++) {
        if (c + 1 < NCH) PRODUCE(c + 1, st ^ 1);

        int aoff = st * A_BUF_F;
        int boff = OFF_B + st * B_BUF_F;
#pragma unroll
        for (int ks = 0; ks < 2; ks++) {
            // B: 4 fragments (this warp's 32 cols), both splits per LDS.128
            uint32_t bf[2][4][2];
#pragma unroll
            for (int tn = 0; tn < 4; tn++) {
                int nblk = warp_n * 4 + tn;
                float4 bv = *(const float4*)&smf[boff
                    + ((nblk * 2 + ks) * 32 + pc) * 4];
                bf[0][tn][0] = __float_as_uint(bv.x);
                bf[0][tn][1] = __float_as_uint(bv.y);
                bf[1][tn][0] = __float_as_uint(bv.z);
                bf[1][tn][1] = __float_as_uint(bv.w);
            }
            uint32_t af[4][4];
            // A split 1: products A1*B1, A1*B2
#pragma unroll
            for (int tm = 0; tm < 4; tm++) {
                int mblk = warp_m * 4 + tm;
                float4 v1 = *(const float4*)&smf[aoff
                    + ((mblk * 2 + ks) * 32 + pc) * 4];
                af[tm][0] = __float_as_uint(v1.x);
                af[tm][1] = __float_as_uint(v1.y);
                af[tm][2] = __float_as_uint(v1.z);
                af[tm][3] = __float_as_uint(v1.w);
            }
#pragma unroll
            for (int tm = 0; tm < 4; tm++)
#pragma unroll
                for (int tn = 0; tn < 4; tn++) {
                    MMA_F16(acc[tm][tn], af[tm], bf[0][tn]);
                    MMA_F16(acc[tm][tn], af[tm], bf[1][tn]);
                }
            // A split 2 (reuse af registers): product A2*B1
#pragma unroll
            for (int tm = 0; tm < 4; tm++) {
                int mblk = warp_m * 4 + tm;
                float4 v2 = *(const float4*)&smf[aoff + 2048
                    + ((mblk * 2 + ks) * 32 + pc) * 4];
                af[tm][0] = __float_as_uint(v2.x);
                af[tm][1] = __float_as_uint(v2.y);
                af[tm][2] = __float_as_uint(v2.z);
                af[tm][3] = __float_as_uint(v2.w);
            }
#pragma unroll
            for (int tm = 0; tm < 4; tm++)
#pragma unroll
                for (int tn = 0; tn < 4; tn++)
                    MMA_F16(acc[tm][tn], af[tm], bf[0][tn]);
        }

        asm volatile("cp.async.wait_group 0;" ::: "memory");
        __syncthreads();
        st ^= 1;
    }

    // ---------------- epilogue: gelu(c + hbias) * w2, reduce ---------------
    float* shb = &smf[OFF_SHB];
    float* sw2 = &smf[OFF_SW2];
    float* red = &smf[OFF_RED];
#pragma unroll
    for (int tm = 0; tm < 4; tm++) {
        float rs0 = 0.0f, rs1 = 0.0f;
#pragma unroll
        for (int tn = 0; tn < 4; tn++) {
            int cl = warp_n * 32 + tn * 8 + 2 * tig;
            float h0 = shb[cl], h1 = shb[cl + 1];
            float w0 = sw2[cl], w1v = sw2[cl + 1];
            rs0 += gelu_exact(acc[tm][tn][0] + h0) * w0
                 + gelu_exact(acc[tm][tn][1] + h1) * w1v;
            rs1 += gelu_exact(acc[tm][tn][2] + h0) * w0
                 + gelu_exact(acc[tm][tn][3] + h1) * w1v;
        }
        rs0 += __shfl_xor_sync(0xffffffffu, rs0, 1);
        rs0 += __shfl_xor_sync(0xffffffffu, rs0, 2);
        rs1 += __shfl_xor_sync(0xffffffffu, rs1, 1);
        rs1 += __shfl_xor_sync(0xffffffffu, rs1, 2);
        if (tig == 0) {
            int r0 = warp_m * 64 + tm * 16 + g;
            red[r0 * 8 + warp_n]       = rs0;
            red[(r0 + 8) * 8 + warp_n] = rs1;
        }
    }
    __syncthreads();
    if (tid < BMt) {
        float p = 0.0f;
#pragma unroll
        for (int wnn = 0; wnn < 8; wnn++) p += red[tid * 8 + wnn];
        g_part[nt * BSv + mt * BMt + tid] = p;
    }
}

// ---------------- fixed-order partial reduction (deterministic) -----------
__global__ void score_reduce() {
    int i = blockIdx.x * 256 + threadIdx.x;
    float s = 0.0f;
#pragma unroll
    for (int nt = 0; nt < NTt; nt++) s += g_part[nt * BSv + i];
    g_scores[i] = s;
}

// ---------------- entmax-1.5 over S via bisection on tau ------------------
__global__ void __launch_bounds__(1024)
entmax_kernel(const float* __restrict__ attn, const float* __restrict__ b2,
              float* __restrict__ zout) {
    __shared__ float sx[Sv];
    __shared__ float red[33];
    int b = blockIdx.x, tid = threadIdx.x;
    int lane = tid & 31, wid = tid >> 5;
    float b2v = b2[0];
    const float* sc = g_scores + (size_t)b * Sv;
    const float* at = attn + (size_t)b * Sv;

    float loc[4], am[4];
    float mx = -3.4e38f;
#pragma unroll
    for (int j = 0; j < 4; j++) {
        int i = tid + j * 1024;
        float a = at[i]; am[j] = a;
        float v = (a == 0.0f) ? -1e9f : sc[i] + b2v;
        v *= 0.5f;
        loc[j] = v;
        mx = fmaxf(mx, v);
    }
#pragma unroll
    for (int o = 16; o; o >>= 1) mx = fmaxf(mx, __shfl_xor_sync(0xffffffffu, mx, o));
    if (lane == 0) red[wid] = mx;
    __syncthreads();
    if (wid == 0) {
        float m = red[lane];
#pragma unroll
        for (int o = 16; o; o >>= 1) m = fmaxf(m, __shfl_xor_sync(0xffffffffu, m, o));
        if (lane == 0) red[32] = m;
    }
    __syncthreads();
    float xmax = red[32];
#pragma unroll
    for (int j = 0; j < 4; j++) sx[tid + j * 1024] = loc[j] - xmax;
    __syncthreads();

    float lo = -1.0f, hi = 0.0f;
    for (int it = 0; it < 30; it++) {
        float mid = 0.5f * (lo + hi);
        float s = 0.0f;
#pragma unroll
        for (int j = 0; j < 4; j++) {
            float d = fmaxf(sx[tid + j * 1024] - mid, 0.0f);
            s = fmaf(d, d, s);
        }
#pragma unroll
        for (int o = 16; o; o >>= 1) s += __shfl_xor_sync(0xffffffffu, s, o);
        __syncthreads();
        if (lane == 0) red[wid] = s;
        __syncthreads();
        if (wid == 0) {
            float t = red[lane];
#pragma unroll
            for (int o = 16; o; o >>= 1) t += __shfl_xor_sync(0xffffffffu, t, o);
            if (lane == 0) red[32] = t;
        }
        __syncthreads();
        float tot = red[32];
        if (tot >= 1.0f) lo = mid; else hi = mid;
    }
    float tau = 0.5f * (lo + hi);
#pragma unroll
    for (int j = 0; j < 4; j++) {
        int i = tid + j * 1024;
        float d = fmaxf(sx[i] - tau, 0.0f);
        zout[(size_t)b * Sv + i] = d * d * am[j];
    }
}

// ---------------- Kumaraswamy gate (g == h numerically) -------------------
__global__ void final_kernel(const float* __restrict__ attn, const float* __restrict__ u,
                             const float* __restrict__ b2, float* __restrict__ out,
                             int out_size) {
    int i = blockIdx.x * 256 + threadIdx.x;
    float a_ = attn[i];
    float sc = (a_ == 0.0f) ? -1e9f : g_scores[i] + b2[0];
    float z = out[i];
    float eff = sc + 2.0f * (2.0f * z - 1.0f);
    float aa = softplusf(eff) + 1e-6f;
    float bbk = softplusf(-eff) + 1e-6f;
    float uc = fminf(fmaxf(u[i], 1e-6f), 1.0f - 1e-6f);
    float xk = powf(1.0f - powf(1.0f - uc, 1.0f / bbk), 1.0f / aa);
    float y = -0.1f + 1.2f * xk;
    float h = (fminf(fmaxf(y, 0.0f), 1.0f) > 0.5f) ? 1.0f : 0.0f;
    out[BSv + i] = h * a_;
    if (i == 0 && out_size >= 2 * BSv + 1) out[2 * BSv] = 0.0f;
}

// ---------------- launch ---------------------------------------------------
extern "C" void kernel_launch(void* const* d_in, const int* in_sizes, int n_in,
                              void* d_out, int out_size) {
    (void)in_sizes; (void)n_in;
    const float* emb  = (const float*)d_in[0];
    const float* attn = (const float*)d_in[1];
    const float* u    = (const float*)d_in[2];
    const float* lng  = (const float*)d_in[3];
    const float* lnb  = (const float*)d_in[4];
    const float* w1   = (const float*)d_in[5];
    const float* b1   = (const float*)d_in[6];
    const float* w2   = (const float*)d_in[7];
    const float* b2   = (const float*)d_in[8];
    float* out = (float*)d_out;

    cudaFuncSetAttribute(gemm_fp16, cudaFuncAttributeMaxDynamicSharedMemorySize,
                         SMEM_BYTES);

    split_w_frag<<<(Hv * Dv) / 256, 256>>>(w1, lng);
    prep_hbias<<<Hv / 8, 256>>>(w1, lnb, b1);
    ln_split_fused<<<NMT, 256>>>(emb, attn);
    gemm_fp16<<<dim3(NTt, NMT), 512, SMEM_BYTES>>>(w2);
    score_reduce<<<BSv / 256, 256>>>();
    entmax_kernel<<<Bv, 1024>>>(attn, b2, out);
    final_kernel<<<BSv / 256, 256>>>(attn, u, b2, out, out_size);
}

// round 16
// speedup vs baseline: 1.2806x; 1.2806x over previous
#include <cuda_runtime.h>
#include <cuda_fp16.h>
#include <math.h>
#include <stdint.h>

// Problem shapes (fixed by the dataset)
#define Bv   32
#define Sv   4096
#define BSv  (Bv * Sv)      // 131072 rows
#define Dv   768            // K
#define Hv   1024           // N

#define BMt  128            // CTA M tile
#define BNt  256            // CTA N tile
#define NTt  (Hv / BNt)     // 4 N-tiles
#define NCH  (Dv / 32)      // 24 32-wide k-slices (g_Af granularity)
#define NCH2 (Dv / 64)      // 12 GEMM chunks of 64
#define NMT  (BSv / BMt)    // 1024 M tiles

// smem layout (float indices) -- 2-stage pipeline, BK=64 chunks
// A stage = 8192 floats (two 4096-float halves, each [sp2][mblk8][ks2][slot32][4f])
// B stage = 16384 floats (two 8192-float halves, each [nblk32][ks2][slot32][4f])
#define A_STG_F 8192
#define B_STG_F 16384
#define OFF_B   16384       // after 2 A stages
#define OFF_SHB 49152       // after 2 B stages
#define OFF_SW2 49408
#define OFF_RED 49664       // 128 x 4 floats
#define SMEM_FLOATS 50176
#define SMEM_BYTES  (SMEM_FLOATS * 4)   // 200704

// ---------------- scratch (static device globals; no allocation) ----------
__device__ float g_scores[BSv];
__device__ float g_part[NTt * BSv];
// W split into 2 fp16 parts, FRAGMENT-MAJOR, splits interleaved per 16B slot:
// [kc 24][nblk 128][ks 2][slot 32][sp0: 4 halfs | sp1: 4 halfs]
__device__ __align__(16) __half g_Wf[24 * 128 * 2 * 32 * 8];
// A (LN-normalized, 2-way fp16 split), FRAGMENT-MAJOR per (mtile, kc):
// [mtile 1024][kc 24][16KB fragment buffer (1024 x uint4)]
__device__ uint4 g_Af[(size_t)NMT * NCH * 1024];   // 402MB
__device__ float g_hbias[Hv];

// ---------------- helpers ---------------------------------------------------
#define MMA_F16(c, a, b)                                                        \
    asm volatile("mma.sync.aligned.m16n8k16.row.col.f32.f16.f16.f32 "          \
                 "{%0,%1,%2,%3}, {%4,%5,%6,%7}, {%8,%9}, {%0,%1,%2,%3};"        \
                 : "+f"((c)[0]), "+f"((c)[1]), "+f"((c)[2]), "+f"((c)[3])       \
                 : "r"((a)[0]), "r"((a)[1]), "r"((a)[2]), "r"((a)[3]),          \
                   "r"((b)[0]), "r"((b)[1]))

__device__ __forceinline__ uint32_t pack_split_lo(float x0, float x1,
                                                  uint32_t &lo2) {
    __half h0 = __float2half_rn(x0), h1 = __float2half_rn(x1);
    __half r0 = __float2half_rn(x0 - __half2float(h0));
    __half r1 = __float2half_rn(x1 - __half2float(h1));
    lo2 = (uint32_t)__half_as_ushort(r0) | ((uint32_t)__half_as_ushort(r1) << 16);
    return (uint32_t)__half_as_ushort(h0) | ((uint32_t)__half_as_ushort(h1) << 16);
}

__device__ __forceinline__ float gelu_exact(float x) {
    return 0.5f * x * (1.0f + erff(x * 0.7071067811865475f));
}
__device__ __forceinline__ float softplusf(float x) {
    return fmaxf(x, 0.0f) + log1pf(expf(-fabsf(x)));
}

// ---------------- prep: fold ln_g into W1, fp16 split, frag-major ---------
__global__ void split_w_frag(const float* __restrict__ w1, const float* __restrict__ lng) {
    int i = blockIdx.x * 256 + threadIdx.x;     // i < Hv*Dv
    int n = i / Dv, k = i % Dv;
    float w = w1[i] * lng[k];
    __half h1 = __float2half_rn(w);
    __half h2 = __float2half_rn(w - __half2float(h1));
    int kc = k >> 5, kl = k & 31, ks = kl >> 4, kk = kl & 15;
    int tig = (kk & 7) >> 1, breg = kk >> 3, lo = kk & 1;
    int nblk = n >> 3, gg = n & 7, slot = tig * 8 + gg;
    size_t base = ((((size_t)kc * 128 + nblk) * 2 + ks) * 32 + slot) * 8
                  + breg * 2 + lo;
    g_Wf[base]     = h1;
    g_Wf[base + 4] = h2;
}

__global__ void prep_hbias(const float* __restrict__ w1, const float* __restrict__ lnb,
                           const float* __restrict__ b1) {
    int h    = blockIdx.x * 8 + (threadIdx.x >> 5);
    int lane = threadIdx.x & 31;
    const float* wr = w1 + (size_t)h * Dv;
    float s = 0.0f;
    for (int d = lane; d < Dv; d += 32) s = fmaf(lnb[d], wr[d], s);
#pragma unroll
    for (int o = 16; o; o >>= 1) s += __shfl_xor_sync(0xffffffffu, s, o);
    if (lane == 0) g_hbias[h] = s + b1[h];
}

// ---------------- fused: LN stats + fp16 split of A, fragment-major -------
__global__ void __launch_bounds__(256) ln_split_fused(const float* __restrict__ emb,
                                                      const float* __restrict__ attn) {
    __shared__ float sstat[512];
    __shared__ float sAr[128], tAr[128];
    __shared__ uint32_t sbuf[4096];
    int mtile = blockIdx.x;
    int tid = threadIdx.x;
    int mm = tid & 127, q2 = tid >> 7;
    int mrow = mtile * BMt + mm;
    float at = attn[mrow];

    {   // pass 1: stats (2 threads per row, each reads 384 floats)
        const float4* ev = (const float4*)(emb + (size_t)mrow * Dv + q2 * 384);
        float s = 0.0f, ss = 0.0f;
#pragma unroll 4
        for (int j = 0; j < 96; j++) {
            float4 v = ev[j];
            float a = v.x * at, b = v.y * at, c = v.z * at, d = v.w * at;
            s += a + b + c + d;
            ss = fmaf(a, a, ss); ss = fmaf(b, b, ss);
            ss = fmaf(c, c, ss); ss = fmaf(d, d, ss);
        }
        sstat[tid] = s;
        sstat[256 + tid] = ss;
    }
    __syncthreads();
    if (tid < 128) {
        float s  = sstat[tid] + sstat[tid + 128];
        float ss = sstat[256 + tid] + sstat[384 + tid];
        float mu  = s * (1.0f / Dv);
        float var = fmaxf(ss * (1.0f / Dv) - mu * mu, 0.0f);
        float rstd = 1.0f / sqrtf(var + 1e-5f);
        sAr[tid] = at * rstd;
        tAr[tid] = mu * rstd;
    }
    __syncthreads();
    float sA = sAr[mm], tA = tAr[mm];
    int gA = mm & 7, hiA = (mm >> 3) & 1, mblkA = mm >> 4;

    // pass 2: per-kc split + fragment staging + coalesced store (L2-hot)
#pragma unroll 1
    for (int kc = 0; kc < NCH; kc++) {
        const float4* ea = (const float4*)(emb + (size_t)mrow * Dv + kc * 32 + q2 * 16);
        float4 v0 = ea[0], v1 = ea[1], v2 = ea[2], v3 = ea[3];
        float av[16] = {v0.x, v0.y, v0.z, v0.w, v1.x, v1.y, v1.z, v1.w,
                        v2.x, v2.y, v2.z, v2.w, v3.x, v3.y, v3.z, v3.w};
#pragma unroll
        for (int c8 = 0; c8 < 2; c8++) {
#pragma unroll
            for (int t = 0; t < 4; t++) {
                float x0 = fmaf(av[c8 * 8 + 2 * t], sA, -tA);
                float x1 = fmaf(av[c8 * 8 + 2 * t + 1], sA, -tA);
                uint32_t p2;
                uint32_t p1 = pack_split_lo(x0, x1, p2);
                int s0 = ((mblkA * 2 + q2) * 32 + t * 8 + gA) * 4 + c8 * 2 + hiA;
                sbuf[s0]        = p1;
                sbuf[s0 + 2048] = p2;
            }
        }
        __syncthreads();
        const uint4* sb4 = (const uint4*)sbuf;
        uint4* dst = g_Af + ((size_t)mtile * NCH + kc) * 1024;
#pragma unroll
        for (int i = 0; i < 4; i++) dst[tid + i * 256] = sb4[tid + i * 256];
        __syncthreads();
    }
}

// ---------------- 3xFP16 GEMM + GELU + w2-dot ------------------------------
// CTA 128x256, 8 warps (2x4), warp tile 64x64, mma m16n8k16,
// products A1B1 + A1B2 + A2B1. BK=64 chunks (12 iterations).
// Inner structure: per ks load af1+af2 once (8 LDS.128, 32 regs), then two
// tn-halves of 4 B fragments (16 regs) + 48 MMAs each -> small LDS bursts
// interleave with MMA blocks (ptxas can rotate 16-reg bf across halves).

__global__ void __launch_bounds__(256, 1)
gemm_fp16(const float* __restrict__ w2) {
    extern __shared__ float smf[];
    uint32_t smemA_addr = (uint32_t)__cvta_generic_to_shared(&smf[0]);
    uint32_t smemB_addr = (uint32_t)__cvta_generic_to_shared(&smf[OFF_B]);

    int nt = blockIdx.x, mt = blockIdx.y;
    int n0 = nt * BNt;
    int tid = threadIdx.x;
    int lane = tid & 31, wid = tid >> 5;
    int warp_m = wid >> 2, warp_n = wid & 3;     // 2 x 4
    int g = lane >> 2, tig = lane & 3;
    int pc = tig * 8 + g;                         // fragment slot index

    if (tid < BNt) {
        smf[OFF_SHB + tid] = g_hbias[n0 + tid];
        smf[OFF_SW2 + tid] = w2[n0 + tid];
    }

    const uint4* aBase = g_Af + (size_t)mt * NCH * 1024;

// Chunk C covers kc = 2C (half 0) and 2C+1 (half 1).
// A: 2048 lines (8/thread). B: 4096 lines (16/thread). One commit group.
#define PRODUCE(C, BUF)                                                         \
    do {                                                                        \
        _Pragma("unroll")                                                       \
        for (int i_ = 0; i_ < 8; i_++) {                                        \
            int L_ = i_ * 256 + tid;                                            \
            int half_ = L_ >> 10, line_ = L_ & 1023;                            \
            const uint4* asrc_ = aBase + ((C) * 2 + half_) * 1024 + line_;      \
            uint32_t sa_ = smemA_addr                                           \
                + (uint32_t)((BUF) * (A_STG_F * 4) + L_ * 16);                  \
            asm volatile("cp.async.cg.shared.global [%0], [%1], 16;"            \
                         :: "r"(sa_), "l"(asrc_) : "memory");                   \
        }                                                                       \
        _Pragma("unroll")                                                       \
        for (int i_ = 0; i_ < 16; i_++) {                                       \
            int L_ = i_ * 256 + tid;                                            \
            int half_ = L_ >> 11, line_ = L_ & 2047;                            \
            int slot_ = line_ & 31, ks_ = (line_ >> 5) & 1, nbl_ = line_ >> 6;  \
            size_t gidx_ = ((((size_t)((C) * 2 + half_) * 128 + nt * 32 + nbl_) \
                            * 2 + ks_) * 32 + slot_) * 8;                       \
            uint32_t sb_ = smemB_addr                                           \
                + (uint32_t)((BUF) * (B_STG_F * 4) + L_ * 16);                  \
            asm volatile("cp.async.cg.shared.global [%0], [%1], 16;"            \
                         :: "r"(sb_), "l"(g_Wf + gidx_) : "memory");            \
        }                                                                       \
        asm volatile("cp.async.commit_group;" ::: "memory");                    \
    } while (0)

    float acc[4][8][4];
#pragma unroll
    for (int tm = 0; tm < 4; tm++)
#pragma unroll
        for (int tn = 0; tn < 8; tn++)
#pragma unroll
            for (int e = 0; e < 4; e++) acc[tm][tn][e] = 0.0f;

    PRODUCE(0, 0);
    asm volatile("cp.async.wait_group 0;" ::: "memory");
    __syncthreads();

    int st = 0;
#pragma unroll 1
    for (int c = 0; c < NCH2; c++) {
        if (c + 1 < NCH2) PRODUCE(c + 1, st ^ 1);

        int aoff = st * A_STG_F;
        int boff = OFF_B + st * B_STG_F;
#pragma unroll
        for (int ks = 0; ks < 4; ks++) {
            int ab = aoff + (ks >> 1) * 4096;
            int bb = boff + (ks >> 1) * 8192;
            int ks2 = ks & 1;
            // A fragments for this ks: both splits (8 LDS.128, 32 regs)
            uint32_t af1[4][4], af2[4][4];
#pragma unroll
            for (int tm = 0; tm < 4; tm++) {
                int mblk = warp_m * 4 + tm;
                float4 v1 = *(const float4*)&smf[ab
                    + ((mblk * 2 + ks2) * 32 + pc) * 4];
                af1[tm][0] = __float_as_uint(v1.x);
                af1[tm][1] = __float_as_uint(v1.y);
                af1[tm][2] = __float_as_uint(v1.z);
                af1[tm][3] = __float_as_uint(v1.w);
                float4 v2 = *(const float4*)&smf[ab + 2048
                    + ((mblk * 2 + ks2) * 32 + pc) * 4];
                af2[tm][0] = __float_as_uint(v2.x);
                af2[tm][1] = __float_as_uint(v2.y);
                af2[tm][2] = __float_as_uint(v2.z);
                af2[tm][3] = __float_as_uint(v2.w);
            }
            // two tn-halves: 4 B fragments (16 regs) + 48 MMAs each
#pragma unroll
            for (int h = 0; h < 2; h++) {
                uint32_t bf[2][4][2];
#pragma unroll
                for (int tn = 0; tn < 4; tn++) {
                    int nblk = warp_n * 8 + h * 4 + tn;
                    float4 bv = *(const float4*)&smf[bb
                        + ((nblk * 2 + ks2) * 32 + pc) * 4];
                    bf[0][tn][0] = __float_as_uint(bv.x);
                    bf[0][tn][1] = __float_as_uint(bv.y);
                    bf[1][tn][0] = __float_as_uint(bv.z);
                    bf[1][tn][1] = __float_as_uint(bv.w);
                }
#pragma unroll
                for (int tm = 0; tm < 4; tm++)
#pragma unroll
                    for (int tn = 0; tn < 4; tn++) {
                        MMA_F16(acc[tm][h * 4 + tn], af1[tm], bf[0][tn]);
                        MMA_F16(acc[tm][h * 4 + tn], af1[tm], bf[1][tn]);
                        MMA_F16(acc[tm][h * 4 + tn], af2[tm], bf[0][tn]);
                    }
            }
        }

        asm volatile("cp.async.wait_group 0;" ::: "memory");
        __syncthreads();
        st ^= 1;
    }

    // ---------------- epilogue: gelu(c + hbias) * w2, reduce ---------------
    float* shb = &smf[OFF_SHB];
    float* sw2 = &smf[OFF_SW2];
    float* red = &smf[OFF_RED];
#pragma unroll
    for (int tm = 0; tm < 4; tm++) {
        float rs0 = 0.0f, rs1 = 0.0f;
#pragma unroll
        for (int tn = 0; tn < 8; tn++) {
            int cl = warp_n * 64 + tn * 8 + 2 * tig;
            float h0 = shb[cl], h1 = shb[cl + 1];
            float w0 = sw2[cl], w1v = sw2[cl + 1];
            rs0 += gelu_exact(acc[tm][tn][0] + h0) * w0
                 + gelu_exact(acc[tm][tn][1] + h1) * w1v;
            rs1 += gelu_exact(acc[tm][tn][2] + h0) * w0
                 + gelu_exact(acc[tm][tn][3] + h1) * w1v;
        }
        rs0 += __shfl_xor_sync(0xffffffffu, rs0, 1);
        rs0 += __shfl_xor_sync(0xffffffffu, rs0, 2);
        rs1 += __shfl_xor_sync(0xffffffffu, rs1, 1);
        rs1 += __shfl_xor_sync(0xffffffffu, rs1, 2);
        if (tig == 0) {
            int r0 = warp_m * 64 + tm * 16 + g;
            red[r0 * 4 + warp_n]       = rs0;
            red[(r0 + 8) * 4 + warp_n] = rs1;
        }
    }
    __syncthreads();
    if (tid < BMt) {
        float p = red[tid * 4] + red[tid * 4 + 1]
                + red[tid * 4 + 2] + red[tid * 4 + 3];
        g_part[nt * BSv + mt * BMt + tid] = p;
    }
}

// ---------------- fixed-order partial reduction (deterministic) -----------
__global__ void score_reduce() {
    int i = blockIdx.x * 256 + threadIdx.x;
    float s = 0.0f;
#pragma unroll
    for (int nt = 0; nt < NTt; nt++) s += g_part[nt * BSv + i];
    g_scores[i] = s;
}

// ---------------- entmax-1.5 over S via bisection on tau ------------------
__global__ void __launch_bounds__(1024)
entmax_kernel(const float* __restrict__ attn, const float* __restrict__ b2,
              float* __restrict__ zout) {
    __shared__ float sx[Sv];
    __shared__ float red[33];
    int b = blockIdx.x, tid = threadIdx.x;
    int lane = tid & 31, wid = tid >> 5;
    float b2v = b2[0];
    const float* sc = g_scores + (size_t)b * Sv;
    const float* at = attn + (size_t)b * Sv;

    float loc[4], am[4];
    float mx = -3.4e38f;
#pragma unroll
    for (int j = 0; j < 4; j++) {
        int i = tid + j * 1024;
        float a = at[i]; am[j] = a;
        float v = (a == 0.0f) ? -1e9f : sc[i] + b2v;
        v *= 0.5f;
        loc[j] = v;
        mx = fmaxf(mx, v);
    }
#pragma unroll
    for (int o = 16; o; o >>= 1) mx = fmaxf(mx, __shfl_xor_sync(0xffffffffu, mx, o));
    if (lane == 0) red[wid] = mx;
    __syncthreads();
    if (wid == 0) {
        float m = red[lane];
#pragma unroll
        for (int o = 16; o; o >>= 1) m = fmaxf(m, __shfl_xor_sync(0xffffffffu, m, o));
        if (lane == 0) red[32] = m;
    }
    __syncthreads();
    float xmax = red[32];
#pragma unroll
    for (int j = 0; j < 4; j++) sx[tid + j * 1024] = loc[j] - xmax;
    __syncthreads();

    float lo = -1.0f, hi = 0.0f;
    for (int it = 0; it < 30; it++) {
        float mid = 0.5f * (lo + hi);
        float s = 0.0f;
#pragma unroll
        for (int j = 0; j < 4; j++) {
            float d = fmaxf(sx[tid + j * 1024] - mid, 0.0f);
            s = fmaf(d, d, s);
        }
#pragma unroll
        for (int o = 16; o; o >>= 1) s += __shfl_xor_sync(0xffffffffu, s, o);
        __syncthreads();
        if (lane == 0) red[wid] = s;
        __syncthreads();
        if (wid == 0) {
            float t = red[lane];
#pragma unroll
            for (int o = 16; o; o >>= 1) t += __shfl_xor_sync(0xffffffffu, t, o);
            if (lane == 0) red[32] = t;
        }
        __syncthreads();
        float tot = red[32];
        if (tot >= 1.0f) lo = mid; else hi = mid;
    }
    float tau = 0.5f * (lo + hi);
#pragma unroll
    for (int j = 0; j < 4; j++) {
        int i = tid + j * 1024;
        float d = fmaxf(sx[i] - tau, 0.0f);
        zout[(size_t)b * Sv + i] = d * d * am[j];
    }
}

// ---------------- Kumaraswamy gate (g == h numerically) -------------------
__global__ void final_kernel(const float* __restrict__ attn, const float* __restrict__ u,
                             const float* __restrict__ b2, float* __restrict__ out,
                             int out_size) {
    int i = blockIdx.x * 256 + threadIdx.x;
    float a_ = attn[i];
    float sc = (a_ == 0.0f) ? -1e9f : g_scores[i] + b2[0];
    float z = out[i];
    float eff = sc + 2.0f * (2.0f * z - 1.0f);
    float aa = softplusf(eff) + 1e-6f;
    float bbk = softplusf(-eff) + 1e-6f;
    float uc = fminf(fmaxf(u[i], 1e-6f), 1.0f - 1e-6f);
    float xk = powf(1.0f - powf(1.0f - uc, 1.0f / bbk), 1.0f / aa);
    float y = -0.1f + 1.2f * xk;
    float h = (fminf(fmaxf(y, 0.0f), 1.0f) > 0.5f) ? 1.0f : 0.0f;
    out[BSv + i] = h * a_;
    if (i == 0 && out_size >= 2 * BSv + 1) out[2 * BSv] = 0.0f;
}

// ---------------- launch ---------------------------------------------------
extern "C" void kernel_launch(void* const* d_in, const int* in_sizes, int n_in,
                              void* d_out, int out_size) {
    (void)in_sizes; (void)n_in;
    const float* emb  = (const float*)d_in[0];
    const float* attn = (const float*)d_in[1];
    const float* u    = (const float*)d_in[2];
    const float* lng  = (const float*)d_in[3];
    const float* lnb  = (const float*)d_in[4];
    const float* w1   = (const float*)d_in[5];
    const float* b1   = (const float*)d_in[6];
    const float* w2   = (const float*)d_in[7];
    const float* b2   = (const float*)d_in[8];
    float* out = (float*)d_out;

    cudaFuncSetAttribute(gemm_fp16, cudaFuncAttributeMaxDynamicSharedMemorySize,
                         SMEM_BYTES);

    split_w_frag<<<(Hv * Dv) / 256, 256>>>(w1, lng);
    prep_hbias<<<Hv / 8, 256>>>(w1, lnb, b1);
    ln_split_fused<<<NMT, 256>>>(emb, attn);
    gemm_fp16<<<dim3(NTt, NMT), 256, SMEM_BYTES>>>(w2);
    score_reduce<<<BSv / 256, 256>>>();
    entmax_kernel<<<Bv, 1024>>>(attn, b2, out);
    final_kernel<<<BSv / 256, 256>>>(attn, u, b2, out, out_size);
}